// round 1
// baseline (speedup 1.0000x reference)
#include <cuda_runtime.h>
#include <cstdint>
#include <cstddef>

#define B_    2
#define L_    192
#define H_    512
#define NH_   8
#define ML_   (B_*L_)     // 384 rows (b,l) flattened
#define TROWS_ 383        // distinct position diffs: [-191, 191]

// ---------------- scratch (device globals; no allocation allowed) ----------------
static __device__ __align__(16) float d_T[4 * TROWS_ * H_];   // 4 pe tables
static __device__ __align__(16) float d_kproj[ML_ * H_];
static __device__ __align__(16) float d_qproj[ML_ * H_];
static __device__ __align__(16) float d_vproj[ML_ * H_];
static __device__ __align__(16) float d_u[ML_ * H_];          // q_proj + v_bias
static __device__ __align__(16) float d_g[ML_ * NH_ * H_];    // u_head @ Wr_head
static __device__ float d_c0[ML_ * NH_];                      // u_head . br_head
static __device__ float d_Cterm[ML_ * NH_];                   // u_bias . k_proj_head
static __device__ __align__(16) float d_attnout[ML_ * H_];

// ---------------- generic tiled SGEMM: C = A * op(B) + bias -----------------
// TRANSB=true : C[m,n] = sum_k A[m*lda+k] * B[n*ldb+k]   (A row-major, B "NT")
// TRANSB=false: C[m,n] = sum_k A[m*lda+k] * B[k*ldb+n]   ("NN")
// block = 256 threads, 64x64 tile, BK=16, 4x4 per-thread microtile.
template<bool TRANSB>
__device__ __forceinline__ void gemm_tile(
    const float* __restrict__ A, int lda,
    const float* __restrict__ B, int ldb,
    const float* __restrict__ bias,
    float* __restrict__ C, int ldc,
    int M, int N, int K)
{
    __shared__ float As[16][68];
    __shared__ float Bs[16][68];
    const int tid = threadIdx.x;
    const int tx = tid & 15, ty = tid >> 4;
    const int m0 = blockIdx.y * 64, n0 = blockIdx.x * 64;
    float acc[4][4];
#pragma unroll
    for (int i = 0; i < 4; ++i)
#pragma unroll
        for (int j = 0; j < 4; ++j) acc[i][j] = 0.f;

    const int lm = tid >> 2;          // 0..63
    const int lk = (tid & 3) * 4;     // 0,4,8,12

    for (int k0 = 0; k0 < K; k0 += 16) {
        // A tile (float4 along k)
        float4 av = make_float4(0.f, 0.f, 0.f, 0.f);
        if (m0 + lm < M)
            av = *reinterpret_cast<const float4*>(A + (size_t)(m0 + lm) * lda + k0 + lk);
        As[lk + 0][lm] = av.x; As[lk + 1][lm] = av.y;
        As[lk + 2][lm] = av.z; As[lk + 3][lm] = av.w;
        // B tile
        if (TRANSB) {
            float4 bv = make_float4(0.f, 0.f, 0.f, 0.f);
            if (n0 + lm < N)
                bv = *reinterpret_cast<const float4*>(B + (size_t)(n0 + lm) * ldb + k0 + lk);
            Bs[lk + 0][lm] = bv.x; Bs[lk + 1][lm] = bv.y;
            Bs[lk + 2][lm] = bv.z; Bs[lk + 3][lm] = bv.w;
        } else {
            const int bk = tid >> 4;          // 0..15
            const int bn = (tid & 15) * 4;    // 0..60
            float4 bv = make_float4(0.f, 0.f, 0.f, 0.f);
            if (n0 + bn < N)
                bv = *reinterpret_cast<const float4*>(B + (size_t)(k0 + bk) * ldb + n0 + bn);
            *reinterpret_cast<float4*>(&Bs[bk][bn]) = bv;
        }
        __syncthreads();
#pragma unroll
        for (int kk = 0; kk < 16; ++kk) {
            float a[4], bb[4];
#pragma unroll
            for (int i = 0; i < 4; ++i) a[i] = As[kk][ty * 4 + i];
#pragma unroll
            for (int j = 0; j < 4; ++j) bb[j] = Bs[kk][tx * 4 + j];
#pragma unroll
            for (int i = 0; i < 4; ++i)
#pragma unroll
                for (int j = 0; j < 4; ++j) acc[i][j] += a[i] * bb[j];
        }
        __syncthreads();
    }
    const int mo = m0 + ty * 4, no = n0 + tx * 4;
#pragma unroll
    for (int i = 0; i < 4; ++i) {
        if (mo + i < M) {
#pragma unroll
            for (int j = 0; j < 4; ++j) {
                if (no + j < N) {
                    float v = acc[i][j];
                    if (bias) v += bias[no + j];
                    C[(size_t)(mo + i) * ldc + no + j] = v;
                }
            }
        }
    }
}

// ---------------- stage 1: q/k/v projections (batched over z) ----------------
__global__ void __launch_bounds__(256) k_qkv(
    const float* __restrict__ key, const float* __restrict__ query, const float* __restrict__ value,
    const float* __restrict__ Wk, const float* __restrict__ bk,
    const float* __restrict__ Wq, const float* __restrict__ bq,
    const float* __restrict__ Wv, const float* __restrict__ bv)
{
    const float* A; const float* W; const float* bias; float* C;
    if (blockIdx.z == 0)      { A = key;   W = Wk; bias = bk; C = d_kproj; }
    else if (blockIdx.z == 1) { A = query; W = Wq; bias = bq; C = d_qproj; }
    else                      { A = value; W = Wv; bias = bv; C = d_vproj; }
    gemm_tile<true>(A, H_, W, H_, bias, C, H_, ML_, H_, H_);
}

// ---------------- stage 2: pe tables T_j[r,h'] = pe[r+321,:256] . W_fus[h', j*256: ] ----
__global__ void __launch_bounds__(256) k_tables(const float* __restrict__ pe,
                                                const float* __restrict__ W_fus)
{
    const int z = blockIdx.z;
    gemm_tile<true>(pe + 321 * H_, H_, W_fus + z * 256, 2 * H_, nullptr,
                    d_T + (size_t)z * TROWS_ * H_, H_, TROWS_, H_, 256);
}

// ---------------- stage 3a: u = q_proj + v_bias ; c0 ; Cterm ----------------
__global__ void __launch_bounds__(512) k_prep(const float* __restrict__ v_bias,
                                              const float* __restrict__ u_bias,
                                              const float* __restrict__ br)
{
    const int m = blockIdx.x;
    const int h = threadIdx.x;
    float u = d_qproj[(size_t)m * H_ + h] + v_bias[h];
    d_u[(size_t)m * H_ + h] = u;
    float p1 = u * br[h];
    float p2 = u_bias[h] * d_kproj[(size_t)m * H_ + h];
#pragma unroll
    for (int s = 16; s > 0; s >>= 1) {
        p1 += __shfl_xor_sync(0xffffffffu, p1, s);
        p2 += __shfl_xor_sync(0xffffffffu, p2, s);
    }
    __shared__ float s1[16], s2[16];
    if ((h & 31) == 0) { s1[h >> 5] = p1; s2[h >> 5] = p2; }
    __syncthreads();
    if (h < NH_) {
        d_c0[(size_t)m * NH_ + h]    = s1[2 * h] + s1[2 * h + 1];
        d_Cterm[(size_t)m * NH_ + h] = s2[2 * h] + s2[2 * h + 1];
    }
}

// ---------------- stage 3b: g[m,n,h'] = sum_d u[m,n*64+d] * Wr[n*64+d, h'] ----
__global__ void __launch_bounds__(256) k_g(const float* __restrict__ Wr)
{
    const int z = blockIdx.z;  // head
    gemm_tile<false>(d_u + z * 64, H_, Wr + (size_t)z * 64 * H_, H_, nullptr,
                     d_g + (size_t)z * H_, NH_ * H_, ML_, H_, 64);
}

// ---------------- stage 4: fused scores + softmax + attn@V per (b,q) ----------------
__global__ void __launch_bounds__(256, 2) k_attn(
    const float* __restrict__ b_fus,
    const int* __restrict__ pos_s,
    const int* __restrict__ pos_e,
    const int* __restrict__ seq_len)
{
    __shared__ __align__(16) float g_s[NH_][H_];   // 16 KB
    __shared__ __align__(16) float qpb[H_];
    __shared__ __align__(16) float bfs[H_];
    __shared__ float sc[NH_][L_];                  // 6 KB
    __shared__ int ksp[L_], kep[L_];

    const int m = blockIdx.x;          // b*L + q
    const int b = m / L_;
    const int tid = threadIdx.x;
    const int lane = tid & 31;
    const int warp = tid >> 5;

    for (int i = tid; i < NH_ * H_; i += 256) (&g_s[0][0])[i] = d_g[(size_t)m * (NH_ * H_) + i];
    for (int i = tid; i < H_; i += 256) { qpb[i] = d_qproj[(size_t)m * H_ + i]; bfs[i] = b_fus[i]; }
    for (int i = tid; i < L_; i += 256) { ksp[i] = pos_s[b * L_ + i]; kep[i] = pos_e[b * L_ + i]; }
    const int psq = pos_s[m], peq = pos_e[m];
    const int slen = seq_len[b];
    __syncthreads();

    const float* __restrict__ kbase = d_kproj + (size_t)b * L_ * H_;

    // warps take k in pairs (k0 = warp + 16*kp, k1 = k0+8) -> no per-k block sync
    for (int kp = 0; kp < 12; ++kp) {
        const int k0 = warp + kp * 16;
        const int k1 = k0 + 8;
        const float* p00 = d_T + (size_t)(0 * TROWS_ + psq - ksp[k0] + 191) * H_;
        const float* p01 = d_T + (size_t)(1 * TROWS_ + psq - kep[k0] + 191) * H_;
        const float* p02 = d_T + (size_t)(2 * TROWS_ + peq - ksp[k0] + 191) * H_;
        const float* p03 = d_T + (size_t)(3 * TROWS_ + peq - kep[k0] + 191) * H_;
        const float* p10 = d_T + (size_t)(0 * TROWS_ + psq - ksp[k1] + 191) * H_;
        const float* p11 = d_T + (size_t)(1 * TROWS_ + psq - kep[k1] + 191) * H_;
        const float* p12 = d_T + (size_t)(2 * TROWS_ + peq - ksp[k1] + 191) * H_;
        const float* p13 = d_T + (size_t)(3 * TROWS_ + peq - kep[k1] + 191) * H_;
        const float* kr0 = kbase + (size_t)k0 * H_;
        const float* kr1 = kbase + (size_t)k1 * H_;

        float acc0[8], acc1[8];
#pragma unroll
        for (int nn = 0; nn < 8; ++nn) { acc0[nn] = 0.f; acc1[nn] = 0.f; }

#pragma unroll
        for (int i = 0; i < 4; ++i) {
            const int h = lane * 4 + i * 128;
            float4 t;
            // relu(T1+T2+T3+T4 + b_fus) for k0
            float4 r0 = *reinterpret_cast<const float4*>(p00 + h);
            t = *reinterpret_cast<const float4*>(p01 + h); r0.x += t.x; r0.y += t.y; r0.z += t.z; r0.w += t.w;
            t = *reinterpret_cast<const float4*>(p02 + h); r0.x += t.x; r0.y += t.y; r0.z += t.z; r0.w += t.w;
            t = *reinterpret_cast<const float4*>(p03 + h); r0.x += t.x; r0.y += t.y; r0.z += t.z; r0.w += t.w;
            float4 bfv = *reinterpret_cast<const float4*>(&bfs[h]);
            r0.x = fmaxf(r0.x + bfv.x, 0.f); r0.y = fmaxf(r0.y + bfv.y, 0.f);
            r0.z = fmaxf(r0.z + bfv.z, 0.f); r0.w = fmaxf(r0.w + bfv.w, 0.f);
            // same for k1
            float4 r1 = *reinterpret_cast<const float4*>(p10 + h);
            t = *reinterpret_cast<const float4*>(p11 + h); r1.x += t.x; r1.y += t.y; r1.z += t.z; r1.w += t.w;
            t = *reinterpret_cast<const float4*>(p12 + h); r1.x += t.x; r1.y += t.y; r1.z += t.z; r1.w += t.w;
            t = *reinterpret_cast<const float4*>(p13 + h); r1.x += t.x; r1.y += t.y; r1.z += t.z; r1.w += t.w;
            r1.x = fmaxf(r1.x + bfv.x, 0.f); r1.y = fmaxf(r1.y + bfv.y, 0.f);
            r1.z = fmaxf(r1.z + bfv.z, 0.f); r1.w = fmaxf(r1.w + bfv.w, 0.f);

            // q.k term (head = (lane<16 ? 2i : 2i+1))
            float4 kv0 = *reinterpret_cast<const float4*>(kr0 + h);
            float4 kv1 = *reinterpret_cast<const float4*>(kr1 + h);
            float4 qv  = *reinterpret_cast<const float4*>(&qpb[h]);
            float qk0 = qv.x * kv0.x + qv.y * kv0.y + qv.z * kv0.z + qv.w * kv0.w;
            float qk1 = qv.x * kv1.x + qv.y * kv1.y + qv.z * kv1.z + qv.w * kv1.w;
            if (lane < 16) { acc0[2 * i]     += qk0; acc1[2 * i]     += qk1; }
            else           { acc0[2 * i + 1] += qk0; acc1[2 * i + 1] += qk1; }

            // s2 = g[n,:] . relu_vec  (all 8 heads share relu_vec)
#pragma unroll
            for (int nn = 0; nn < 8; ++nn) {
                float4 gv = *reinterpret_cast<const float4*>(&g_s[nn][h]);
                acc0[nn] += gv.x * r0.x + gv.y * r0.y + gv.z * r0.z + gv.w * r0.w;
                acc1[nn] += gv.x * r1.x + gv.y * r1.y + gv.z * r1.z + gv.w * r1.w;
            }
        }
        // lane reduction
#pragma unroll
        for (int nn = 0; nn < 8; ++nn) {
#pragma unroll
            for (int s = 16; s > 0; s >>= 1) {
                acc0[nn] += __shfl_xor_sync(0xffffffffu, acc0[nn], s);
                acc1[nn] += __shfl_xor_sync(0xffffffffu, acc1[nn], s);
            }
        }
        if (lane == 0) {
#pragma unroll
            for (int nn = 0; nn < 8; ++nn) {
                float c0v = d_c0[(size_t)m * NH_ + nn];
                float s0 = (acc0[nn] + d_Cterm[(size_t)(b * L_ + k0) * NH_ + nn] + c0v) * 0.125f;
                float s1v = (acc1[nn] + d_Cterm[(size_t)(b * L_ + k1) * NH_ + nn] + c0v) * 0.125f;
                sc[nn][k0] = (k0 < slen) ? s0  : -1e30f;
                sc[nn][k1] = (k1 < slen) ? s1v : -1e30f;
            }
        }
    }
    __syncthreads();

    // softmax over k, warp = head
    {
        const int n = warp;
        float mx = -3.4e38f;
#pragma unroll
        for (int j = 0; j < 6; ++j) mx = fmaxf(mx, sc[n][lane + 32 * j]);
#pragma unroll
        for (int s = 16; s > 0; s >>= 1) mx = fmaxf(mx, __shfl_xor_sync(0xffffffffu, mx, s));
        float sum = 0.f;
        float ev[6];
#pragma unroll
        for (int j = 0; j < 6; ++j) {
            ev[j] = __expf(sc[n][lane + 32 * j] - mx);
            sum += ev[j];
        }
#pragma unroll
        for (int s = 16; s > 0; s >>= 1) sum += __shfl_xor_sync(0xffffffffu, sum, s);
        const float inv = 1.f / sum;
#pragma unroll
        for (int j = 0; j < 6; ++j) sc[n][lane + 32 * j] = ev[j] * inv;
    }
    __syncthreads();

    // out[m, h] = sum_k attn[n,k] * v_proj[b,k,h]   (n = h>>6 == warp for h = 2*tid)
    {
        const float* __restrict__ vbase = d_vproj + (size_t)b * L_ * H_;
        const int h = tid * 2;
        const int n = warp;
        float o0 = 0.f, o1 = 0.f;
#pragma unroll 4
        for (int k = 0; k < L_; ++k) {
            const float a = sc[n][k];
            const float2 vv = *reinterpret_cast<const float2*>(vbase + (size_t)k * H_ + h);
            o0 += a * vv.x; o1 += a * vv.y;
        }
        d_attnout[(size_t)m * H_ + h]     = o0;
        d_attnout[(size_t)m * H_ + h + 1] = o1;
    }
}

// ---------------- stage 5: output projection ----------------
__global__ void __launch_bounds__(256) k_ff(const float* __restrict__ Wff,
                                            const float* __restrict__ bff,
                                            float* __restrict__ out)
{
    gemm_tile<true>(d_attnout, H_, Wff, H_, bff, out, H_, ML_, H_, H_);
}

// ---------------- launch ----------------
extern "C" void kernel_launch(void* const* d_in, const int* in_sizes, int n_in,
                              void* d_out, int out_size)
{
    (void)n_in; (void)out_size;
    const float* key     = (const float*)d_in[0];
    const float* query   = (const float*)d_in[1];
    const float* value   = (const float*)d_in[2];
    const int*   seq_len = (const int*)d_in[3];
    // lex_num (python scalar 0) may or may not appear as a size-1 input at idx 4
    const int ip = (in_sizes[4] == 1) ? 5 : 4;
    const int*   pos_s  = (const int*)d_in[ip + 0];
    const int*   pos_e  = (const int*)d_in[ip + 1];
    const float* pe     = (const float*)d_in[ip + 2];
    const float* W_fus  = (const float*)d_in[ip + 3];
    const float* b_fus  = (const float*)d_in[ip + 4];
    const float* Wk     = (const float*)d_in[ip + 5];
    const float* bk     = (const float*)d_in[ip + 6];
    const float* Wq     = (const float*)d_in[ip + 7];
    const float* bq     = (const float*)d_in[ip + 8];
    const float* Wv     = (const float*)d_in[ip + 9];
    const float* bv     = (const float*)d_in[ip + 10];
    const float* Wr     = (const float*)d_in[ip + 11];
    const float* br     = (const float*)d_in[ip + 12];
    const float* u_bias = (const float*)d_in[ip + 13];
    const float* v_bias = (const float*)d_in[ip + 14];
    const float* Wff    = (const float*)d_in[ip + 15];
    const float* bff    = (const float*)d_in[ip + 16];

    k_qkv   <<<dim3(8, 6, 3), 256>>>(key, query, value, Wk, bk, Wq, bq, Wv, bv);
    k_tables<<<dim3(8, 6, 4), 256>>>(pe, W_fus);
    k_prep  <<<ML_, 512>>>(v_bias, u_bias, br);
    k_g     <<<dim3(8, 6, 8), 256>>>(Wr);
    k_attn  <<<ML_, 256>>>(b_fus, pos_s, pos_e, seq_len);
    k_ff    <<<dim3(8, 6, 1), 256>>>(Wff, bff, (float*)d_out);
}

// round 2
// speedup vs baseline: 1.2535x; 1.2535x over previous
#include <cuda_runtime.h>
#include <cuda_fp16.h>
#include <cstdint>
#include <cstddef>

#define B_    2
#define L_    192
#define H_    512
#define NH_   8
#define ML_   (B_*L_)     // 384 rows (b,l) flattened
#define TROWS_ 383        // distinct position diffs: [-191, 191]

// ---------------- scratch (device globals; no allocation allowed) ----------------
static __device__ __align__(16) __half d_Th[4 * TROWS_ * H_];   // 4 pe tables (half)
static __device__ __align__(16) float  d_kproj[ML_ * H_];
static __device__ __align__(16) float  d_qproj[ML_ * H_];
static __device__ __align__(16) __half d_vh[ML_ * H_];          // v projection (half)
static __device__ __align__(16) float  d_u[ML_ * H_];           // q_proj + v_bias
static __device__ __align__(16) __half d_gh[ML_ * NH_ * H_];    // u_head @ Wr_head (half)
static __device__ __align__(16) float  d_qk[2 * NH_ * L_ * L_]; // per-head q.k scores
static __device__ __align__(16) float  d_c0[ML_ * NH_];         // u_head . br_head
static __device__ __align__(16) float  d_Cterm[ML_ * NH_];      // u_bias . k_proj_head
static __device__ __align__(16) float  d_attnout[ML_ * H_];

__device__ __forceinline__ float st_conv(float v, float*)  { return v; }
__device__ __forceinline__ __half st_conv(float v, __half*) { return __float2half(v); }

// ---------------- generic tiled SGEMM: C = A * op(B) + bias -----------------
// TRANSB=true : C[m,n] = sum_k A[m*lda+k] * B[n*ldb+k]
// TRANSB=false: C[m,n] = sum_k A[m*lda+k] * B[k*ldb+n]
// block = 256 threads, 64x64 tile, BK=16, 4x4 microtile.
template<bool TRANSB, typename OT>
__device__ __forceinline__ void gemm_tile(
    const float* __restrict__ A, int lda,
    const float* __restrict__ B, int ldb,
    const float* __restrict__ bias,
    OT* __restrict__ C, int ldc,
    int M, int N, int K)
{
    __shared__ float As[16][68];
    __shared__ float Bs[16][68];
    const int tid = threadIdx.x;
    const int tx = tid & 15, ty = tid >> 4;
    const int m0 = blockIdx.y * 64, n0 = blockIdx.x * 64;
    float acc[4][4];
#pragma unroll
    for (int i = 0; i < 4; ++i)
#pragma unroll
        for (int j = 0; j < 4; ++j) acc[i][j] = 0.f;

    const int lm = tid >> 2;          // 0..63
    const int lk = (tid & 3) * 4;     // 0,4,8,12

    for (int k0 = 0; k0 < K; k0 += 16) {
        float4 av = make_float4(0.f, 0.f, 0.f, 0.f);
        if (m0 + lm < M)
            av = *reinterpret_cast<const float4*>(A + (size_t)(m0 + lm) * lda + k0 + lk);
        As[lk + 0][lm] = av.x; As[lk + 1][lm] = av.y;
        As[lk + 2][lm] = av.z; As[lk + 3][lm] = av.w;
        if (TRANSB) {
            float4 bv = make_float4(0.f, 0.f, 0.f, 0.f);
            if (n0 + lm < N)
                bv = *reinterpret_cast<const float4*>(B + (size_t)(n0 + lm) * ldb + k0 + lk);
            Bs[lk + 0][lm] = bv.x; Bs[lk + 1][lm] = bv.y;
            Bs[lk + 2][lm] = bv.z; Bs[lk + 3][lm] = bv.w;
        } else {
            const int bk = tid >> 4;          // 0..15
            const int bn = (tid & 15) * 4;    // 0..60
            float4 bv = make_float4(0.f, 0.f, 0.f, 0.f);
            if (n0 + bn < N)
                bv = *reinterpret_cast<const float4*>(B + (size_t)(k0 + bk) * ldb + n0 + bn);
            *reinterpret_cast<float4*>(&Bs[bk][bn]) = bv;
        }
        __syncthreads();
#pragma unroll
        for (int kk = 0; kk < 16; ++kk) {
            float a[4], bb[4];
#pragma unroll
            for (int i = 0; i < 4; ++i) a[i] = As[kk][ty * 4 + i];
#pragma unroll
            for (int j = 0; j < 4; ++j) bb[j] = Bs[kk][tx * 4 + j];
#pragma unroll
            for (int i = 0; i < 4; ++i)
#pragma unroll
                for (int j = 0; j < 4; ++j) acc[i][j] += a[i] * bb[j];
        }
        __syncthreads();
    }
    const int mo = m0 + ty * 4, no = n0 + tx * 4;
#pragma unroll
    for (int i = 0; i < 4; ++i) {
        if (mo + i < M) {
#pragma unroll
            for (int j = 0; j < 4; ++j) {
                if (no + j < N) {
                    float v = acc[i][j];
                    if (bias) v += bias[no + j];
                    C[(size_t)(mo + i) * ldc + no + j] = st_conv(v, (OT*)nullptr);
                }
            }
        }
    }
}

// ---------------- stage 1: q/k/v projections + pe tables (fused) ----------------
__global__ void __launch_bounds__(256) k_pre(
    const float* __restrict__ key, const float* __restrict__ query, const float* __restrict__ value,
    const float* __restrict__ Wk, const float* __restrict__ bk,
    const float* __restrict__ Wq, const float* __restrict__ bq,
    const float* __restrict__ Wv, const float* __restrict__ bv,
    const float* __restrict__ pe, const float* __restrict__ W_fus)
{
    const int z = blockIdx.z;
    if (z == 0) {
        gemm_tile<true>(key, H_, Wk, H_, bk, d_kproj, H_, ML_, H_, H_);
    } else if (z == 1) {
        gemm_tile<true>(query, H_, Wq, H_, bq, d_qproj, H_, ML_, H_, H_);
    } else if (z == 2) {
        gemm_tile<true>(value, H_, Wv, H_, bv, d_vh, H_, ML_, H_, H_);
    } else {
        const int t = z - 3;   // table 0..3
        gemm_tile<true>(pe + 321 * H_, H_, W_fus + t * 256, 2 * H_, nullptr,
                        d_Th + (size_t)t * TROWS_ * H_, H_, TROWS_, H_, 256);
    }
}

// ---------------- stage 2: u = q_proj + v_bias ; c0 ; Cterm ----------------
__global__ void __launch_bounds__(512) k_prep(const float* __restrict__ v_bias,
                                              const float* __restrict__ u_bias,
                                              const float* __restrict__ br)
{
    const int m = blockIdx.x;
    const int h = threadIdx.x;
    float u = d_qproj[(size_t)m * H_ + h] + v_bias[h];
    d_u[(size_t)m * H_ + h] = u;
    float p1 = u * br[h];
    float p2 = u_bias[h] * d_kproj[(size_t)m * H_ + h];
#pragma unroll
    for (int s = 16; s > 0; s >>= 1) {
        p1 += __shfl_xor_sync(0xffffffffu, p1, s);
        p2 += __shfl_xor_sync(0xffffffffu, p2, s);
    }
    __shared__ float s1[16], s2[16];
    if ((h & 31) == 0) { s1[h >> 5] = p1; s2[h >> 5] = p2; }
    __syncthreads();
    if (h < NH_) {
        d_c0[(size_t)m * NH_ + h]    = s1[2 * h] + s1[2 * h + 1];
        d_Cterm[(size_t)m * NH_ + h] = s2[2 * h] + s2[2 * h + 1];
    }
}

// ---------------- stage 3: g (half) + per-head qk GEMMs (fused) ----------------
__global__ void __launch_bounds__(256) k_gqk(const float* __restrict__ Wr)
{
    const int z = blockIdx.z;
    if (z < 8) {
        // g[m, z, f] = sum_d u[m, z*64+d] * Wr[z*64+d, f]
        gemm_tile<false>(d_u + z * 64, H_, Wr + (size_t)z * 64 * H_, H_, nullptr,
                         d_gh + (size_t)z * H_, NH_ * H_, ML_, H_, 64);
    } else {
        if (blockIdx.x >= 3 || blockIdx.y >= 3) return;
        const int idx = z - 8;         // b*8 + n
        const int b = idx >> 3, n = idx & 7;
        gemm_tile<true>(d_qproj + (size_t)b * L_ * H_ + n * 64, H_,
                        d_kproj + (size_t)b * L_ * H_ + n * 64, H_, nullptr,
                        d_qk + (size_t)idx * L_ * L_, L_, L_, L_, 64);
    }
}

__device__ __forceinline__ __half2 shfl_xor_h2(__half2 v, int s) {
    unsigned u = *reinterpret_cast<unsigned*>(&v);
    u = __shfl_xor_sync(0xffffffffu, u, s);
    return *reinterpret_cast<__half2*>(&u);
}

// ---------------- stage 4: fused rel-scores + softmax + attn@V per (b,q) ----------------
__global__ void __launch_bounds__(256, 3) k_attn(
    const float* __restrict__ b_fus,
    const int* __restrict__ pos_s,
    const int* __restrict__ pos_e,
    const int* __restrict__ seq_len)
{
    __shared__ __align__(16) __half g_s[NH_][H_];    // 8 KB
    __shared__ __align__(16) float base_s[NH_][L_];  // 6 KB: qk + Cterm + c0
    __shared__ __align__(16) float sc[NH_][L_];      // 6 KB
    __shared__ int ksp[L_], kep[L_];

    const int m = blockIdx.x;          // b*L + q
    const int b = m / L_;
    const int qi = m % L_;
    const int tid = threadIdx.x;
    const int lane = tid & 31;
    const int warp = tid >> 5;

    // g tile (half): 4096 halves = 512 uint4
    {
        const uint4* src = reinterpret_cast<const uint4*>(d_gh + (size_t)m * (NH_ * H_));
        uint4* dst = reinterpret_cast<uint4*>(&g_s[0][0]);
        for (int i = tid; i < (NH_ * H_) / 8; i += 256) dst[i] = src[i];
    }
    // base = qk + Cterm + c0
    for (int i = tid; i < NH_ * L_; i += 256) {
        const int n = i / L_, k = i % L_;
        base_s[n][k] = d_qk[((size_t)(b * NH_ + n) * L_ + qi) * L_ + k]
                     + d_Cterm[(size_t)(b * L_ + k) * NH_ + n]
                     + d_c0[(size_t)m * NH_ + n];
    }
    for (int i = tid; i < L_; i += 256) { ksp[i] = pos_s[b * L_ + i]; kep[i] = pos_e[b * L_ + i]; }
    const int psq = pos_s[m], peq = pos_e[m];
    const int slen = seq_len[b];

    // b_fus -> half2 regs for this lane's 16 dims: h = lane*8 + i*256
    __half2 bfh[8];
#pragma unroll
    for (int i = 0; i < 2; ++i) {
        const int h = lane * 8 + i * 256;
        float4 f0 = *reinterpret_cast<const float4*>(b_fus + h);
        float4 f1 = *reinterpret_cast<const float4*>(b_fus + h + 4);
        bfh[i * 4 + 0] = __floats2half2_rn(f0.x, f0.y);
        bfh[i * 4 + 1] = __floats2half2_rn(f0.z, f0.w);
        bfh[i * 4 + 2] = __floats2half2_rn(f1.x, f1.y);
        bfh[i * 4 + 3] = __floats2half2_rn(f1.z, f1.w);
    }
    __syncthreads();

    const __half2 hz = __float2half2_rn(0.f);

    for (int kk = warp; kk < L_; kk += 8) {
        const uint4* t0 = reinterpret_cast<const uint4*>(d_Th + (size_t)(0 * TROWS_ + psq - ksp[kk] + 191) * H_);
        const uint4* t1 = reinterpret_cast<const uint4*>(d_Th + (size_t)(1 * TROWS_ + psq - kep[kk] + 191) * H_);
        const uint4* t2 = reinterpret_cast<const uint4*>(d_Th + (size_t)(2 * TROWS_ + peq - ksp[kk] + 191) * H_);
        const uint4* t3 = reinterpret_cast<const uint4*>(d_Th + (size_t)(3 * TROWS_ + peq - kep[kk] + 191) * H_);

        __half2 acc[NH_];
#pragma unroll
        for (int n = 0; n < NH_; ++n) acc[n] = hz;

#pragma unroll
        for (int i = 0; i < 2; ++i) {
            const int u4 = lane + i * 32;       // uint4 index into 512-half row
            uint4 a0 = t0[u4], a1 = t1[u4], a2 = t2[u4], a3 = t3[u4];
            const __half2* h0 = reinterpret_cast<const __half2*>(&a0);
            const __half2* h1 = reinterpret_cast<const __half2*>(&a1);
            const __half2* h2 = reinterpret_cast<const __half2*>(&a2);
            const __half2* h3 = reinterpret_cast<const __half2*>(&a3);
            __half2 r[4];
#pragma unroll
            for (int j = 0; j < 4; ++j) {
                __half2 s = __hadd2(__hadd2(h0[j], h1[j]), __hadd2(h2[j], h3[j]));
                r[j] = __hmax2(__hadd2(s, bfh[i * 4 + j]), hz);
            }
            const int h = lane * 8 + i * 256;
#pragma unroll
            for (int n = 0; n < NH_; ++n) {
                uint4 gg = *reinterpret_cast<const uint4*>(&g_s[n][h]);
                const __half2* gh = reinterpret_cast<const __half2*>(&gg);
#pragma unroll
                for (int j = 0; j < 4; ++j) acc[n] = __hfma2(gh[j], r[j], acc[n]);
            }
        }
        // butterfly reduce (half2 carries 2 partial sums per shuffle)
#pragma unroll
        for (int s = 16; s > 0; s >>= 1) {
#pragma unroll
            for (int n = 0; n < NH_; ++n) acc[n] = __hadd2(acc[n], shfl_xor_h2(acc[n], s));
        }
        if (lane == 0) {
            const bool valid = kk < slen;
#pragma unroll
            for (int n = 0; n < NH_; ++n) {
                float bd = __low2float(acc[n]) + __high2float(acc[n]);
                float s = (bd + base_s[n][kk]) * 0.125f;
                sc[n][kk] = valid ? s : -1e30f;
            }
        }
    }
    __syncthreads();

    // softmax over k, warp = head
    {
        const int n = warp;
        float mx = -3.4e38f;
#pragma unroll
        for (int j = 0; j < 6; ++j) mx = fmaxf(mx, sc[n][lane + 32 * j]);
#pragma unroll
        for (int s = 16; s > 0; s >>= 1) mx = fmaxf(mx, __shfl_xor_sync(0xffffffffu, mx, s));
        float sum = 0.f;
        float ev[6];
#pragma unroll
        for (int j = 0; j < 6; ++j) {
            ev[j] = __expf(sc[n][lane + 32 * j] - mx);
            sum += ev[j];
        }
#pragma unroll
        for (int s = 16; s > 0; s >>= 1) sum += __shfl_xor_sync(0xffffffffu, sum, s);
        const float inv = 1.f / sum;
#pragma unroll
        for (int j = 0; j < 6; ++j) sc[n][lane + 32 * j] = ev[j] * inv;
    }
    __syncthreads();

    // out[m, h] = sum_k attn[n,k] * v_half[b,k,h]   (n = warp for h = 2*tid)
    {
        const __half* __restrict__ vb = d_vh + (size_t)b * L_ * H_;
        const int h = tid * 2;
        const int n = warp;
        float o0 = 0.f, o1 = 0.f;
#pragma unroll 4
        for (int k = 0; k < L_; ++k) {
            const float a = sc[n][k];
            __half2 hv = *reinterpret_cast<const __half2*>(vb + (size_t)k * H_ + h);
            float2 f = __half22float2(hv);
            o0 += a * f.x; o1 += a * f.y;
        }
        d_attnout[(size_t)m * H_ + h]     = o0;
        d_attnout[(size_t)m * H_ + h + 1] = o1;
    }
}

// ---------------- stage 5: output projection ----------------
__global__ void __launch_bounds__(256) k_ff(const float* __restrict__ Wff,
                                            const float* __restrict__ bff,
                                            float* __restrict__ out)
{
    gemm_tile<true>(d_attnout, H_, Wff, H_, bff, out, H_, ML_, H_, H_);
}

// ---------------- launch ----------------
extern "C" void kernel_launch(void* const* d_in, const int* in_sizes, int n_in,
                              void* d_out, int out_size)
{
    (void)n_in; (void)out_size;
    const float* key     = (const float*)d_in[0];
    const float* query   = (const float*)d_in[1];
    const float* value   = (const float*)d_in[2];
    const int*   seq_len = (const int*)d_in[3];
    const int ip = (in_sizes[4] == 1) ? 5 : 4;   // skip lex_num if present
    const int*   pos_s  = (const int*)d_in[ip + 0];
    const int*   pos_e  = (const int*)d_in[ip + 1];
    const float* pe     = (const float*)d_in[ip + 2];
    const float* W_fus  = (const float*)d_in[ip + 3];
    const float* b_fus  = (const float*)d_in[ip + 4];
    const float* Wk     = (const float*)d_in[ip + 5];
    const float* bk     = (const float*)d_in[ip + 6];
    const float* Wq     = (const float*)d_in[ip + 7];
    const float* bq     = (const float*)d_in[ip + 8];
    const float* Wv     = (const float*)d_in[ip + 9];
    const float* bv     = (const float*)d_in[ip + 10];
    const float* Wr     = (const float*)d_in[ip + 11];
    const float* br     = (const float*)d_in[ip + 12];
    const float* u_bias = (const float*)d_in[ip + 13];
    const float* v_bias = (const float*)d_in[ip + 14];
    const float* Wff    = (const float*)d_in[ip + 15];
    const float* bff    = (const float*)d_in[ip + 16];

    k_pre  <<<dim3(8, 6, 7), 256>>>(key, query, value, Wk, bk, Wq, bq, Wv, bv, pe, W_fus);
    k_prep <<<ML_, 512>>>(v_bias, u_bias, br);
    k_gqk  <<<dim3(8, 6, 24), 256>>>(Wr);
    k_attn <<<ML_, 256>>>(b_fus, pos_s, pos_e, seq_len);
    k_ff   <<<dim3(8, 6, 1), 256>>>(Wff, bff, (float*)d_out);
}